// round 14
// baseline (speedup 1.0000x reference)
#include <cuda_runtime.h>
#include <cuda_fp16.h>
#include <math.h>
#include <stdint.h>

#define BB 32
#define TT 1024
#define DD 256
#define HH 341
#define RRR 4
#define NSP 32
#define NFQ 16
#define NPAD 352        // H padded to 352
#define NROWS (BB*TT)   // 32768

// Output layout
#define HARD_OFF  (BB*TT)
#define SCAL_OFF  (HARD_OFF + RRR*BB*TT)
#define PSM_OFF   (SCAL_OFF + 1)
#define RHOE_OFF  (PSM_OFF + RRR)

// Device scratch
__device__ __half g_x0[NROWS*DD];      // fp16 hi of LN output
__device__ __half g_x1[NROWS*DD];      // fp16 residual
__device__ __half g_w0t[NPAD*DD];      // [n][k] transposed w1 hi
__device__ __half g_w1t[NPAD*DD];      // [n][k] transposed w1 residual
__device__ float g_b1p[NPAD];
__device__ float g_w2p[NPAD];
__device__ float g_scores[BB*TT];
__device__ float g_frp[BB*NFQ*DD];
__device__ int   g_seg[BB*TT];
__device__ float g_den[RRR*BB];
__device__ float g_ps[RRR*BB];
__device__ float g_pp[BB*NSP*RRR*DD];
__device__ int   g_ctr;                // last-block counter (reset each run)

__constant__ float c_rho[RRR] = {0.1f, 0.25f, 0.5f, 0.75f};

#define SWZ128(x) ((x) ^ (((x) >> 3) & 0x70))

__device__ __forceinline__ uint32_t smem_u32(const void* p) {
    uint32_t a;
    asm("{ .reg .u64 t; cvta.to.shared.u64 t, %1; cvt.u32.u64 %0, t; }"
        : "=r"(a) : "l"(p));
    return a;
}
__device__ __forceinline__ void cp16(uint32_t dst, const void* src) {
    asm volatile("cp.async.cg.shared.global [%0], [%1], 16;"
                 :: "r"(dst), "l"(src));
}
#define CP_COMMIT() asm volatile("cp.async.commit_group;" ::: "memory")
#define CP_WAIT(n)  asm volatile("cp.async.wait_group %0;" :: "n"(n) : "memory")

__device__ __forceinline__ void ldsm_x4(uint32_t& r0, uint32_t& r1,
                                        uint32_t& r2, uint32_t& r3, uint32_t a) {
    asm volatile("ldmatrix.sync.aligned.m8n8.x4.shared.b16 {%0,%1,%2,%3}, [%4];"
                 : "=r"(r0), "=r"(r1), "=r"(r2), "=r"(r3) : "r"(a));
}
__device__ __forceinline__ void ldsm_x2(uint32_t& r0, uint32_t& r1, uint32_t a) {
    asm volatile("ldmatrix.sync.aligned.m8n8.x2.shared.b16 {%0,%1}, [%2];"
                 : "=r"(r0), "=r"(r1) : "r"(a));
}
__device__ __forceinline__ void mma16816(float* c, const uint32_t* a,
                                         const uint32_t* b) {
    asm volatile("mma.sync.aligned.m16n8k16.row.col.f32.f16.f16.f32 "
                 "{%0,%1,%2,%3}, {%4,%5,%6,%7}, {%8,%9}, {%0,%1,%2,%3};"
                 : "+f"(c[0]), "+f"(c[1]), "+f"(c[2]), "+f"(c[3])
                 : "r"(a[0]), "r"(a[1]), "r"(a[2]), "r"(a[3]),
                   "r"(b[0]), "r"(b[1]));
}
__device__ __forceinline__ float gelu_exact(float x) {
    return 0.5f * x * (1.f + erff(x * 0.7071067811865476f));
}

// ---------------------------------------------------------------------------
// Reductions
// ---------------------------------------------------------------------------
__device__ __forceinline__ float blockReduce1024(float v, float* red) {
    int lane = threadIdx.x & 31, w = threadIdx.x >> 5;
    #pragma unroll
    for (int o = 16; o; o >>= 1) v += __shfl_xor_sync(0xffffffffu, v, o);
    __syncthreads();
    if (lane == 0) red[w] = v;
    __syncthreads();
    if (w == 0) {
        float s = red[lane];
        #pragma unroll
        for (int o = 16; o; o >>= 1) s += __shfl_xor_sync(0xffffffffu, s, o);
        if (lane == 0) red[0] = s;
    }
    __syncthreads();
    return red[0];
}
__device__ __forceinline__ float blockReduce256(float v, float* red) {
    int lane = threadIdx.x & 31, w = threadIdx.x >> 5;
    #pragma unroll
    for (int o = 16; o; o >>= 1) v += __shfl_xor_sync(0xffffffffu, v, o);
    __syncthreads();
    if (lane == 0) red[w] = v;
    __syncthreads();
    if (w == 0) {
        float s = (lane < 8) ? red[lane] : 0.f;
        #pragma unroll
        for (int o = 16; o; o >>= 1) s += __shfl_xor_sync(0xffffffffu, s, o);
        if (lane == 0) red[0] = s;
    }
    __syncthreads();
    return red[0];
}

// ---------------------------------------------------------------------------
// K_split (fused with wsplit): blocks [0,512) do LN+fp16x2 split + fullrep
// partials; blocks [512, 512+NPAD) transpose+pad+split w1 and pad b1/w2.
// ---------------------------------------------------------------------------
__global__ __launch_bounds__(256) void k_split(const float* __restrict__ emb,
                                               const float* __restrict__ attn,
                                               const float* __restrict__ lnw,
                                               const float* __restrict__ lnb,
                                               const float* __restrict__ w1,
                                               const float* __restrict__ b1,
                                               const float* __restrict__ w2) {
    __shared__ float wacc[8*DD];
    int tid = threadIdx.x;
    if (blockIdx.x >= 512) {
        int n = blockIdx.x - 512, k = tid;
        float v = (n < HH) ? w1[(size_t)k*HH + n] : 0.f;
        __half h0 = __float2half_rn(v);
        float r = v - __half2float(h0);
        __half h1 = __float2half_rn(r);
        g_w0t[n*DD + k] = h0;
        g_w1t[n*DD + k] = h1;
        if (k == 0) {
            g_b1p[n] = (n < HH) ? b1[n] : 0.f;
            g_w2p[n] = (n < HH) ? w2[n] : 0.f;
        }
        return;
    }
    int lane = tid & 31, w = tid >> 5;
    int row0 = blockIdx.x * 64;
    int c0 = lane * 8;
    float lw[8], lb[8];
    #pragma unroll
    for (int i = 0; i < 8; i++) { lw[i] = lnw[c0+i]; lb[i] = lnb[c0+i]; }

    float acc[8] = {0,0,0,0,0,0,0,0};
    for (int rr = 0; rr < 8; rr++) {
        int gr = row0 + w*8 + rr;
        float sel = attn[gr];
        const float4* ep = (const float4*)(emb + (size_t)gr*DD + c0);
        float4 e0 = ep[0], e1 = ep[1];
        float e[8] = {e0.x,e0.y,e0.z,e0.w,e1.x,e1.y,e1.z,e1.w};
        #pragma unroll
        for (int i = 0; i < 8; i++) acc[i] += sel * e[i];
        float x[8]; float s = 0.f;
        #pragma unroll
        for (int i = 0; i < 8; i++) { x[i] = e[i]*sel; s += x[i]; }
        #pragma unroll
        for (int o = 16; o; o >>= 1) s += __shfl_xor_sync(0xffffffffu, s, o);
        float mean = s * (1.f/256.f);
        float v = 0.f;
        #pragma unroll
        for (int i = 0; i < 8; i++) { float dl = x[i]-mean; v += dl*dl; }
        #pragma unroll
        for (int o = 16; o; o >>= 1) v += __shfl_xor_sync(0xffffffffu, v, o);
        float rstd = rsqrtf(v*(1.f/256.f) + 1e-5f);
        unsigned int p0[4], p1[4];
        #pragma unroll
        for (int i = 0; i < 8; i += 2) {
            float ya = (x[i]-mean)*rstd*lw[i] + lb[i];
            float yb = (x[i+1]-mean)*rstd*lw[i+1] + lb[i+1];
            __half a0 = __float2half_rn(ya), b0 = __float2half_rn(yb);
            float ra = ya - __half2float(a0), rb = yb - __half2float(b0);
            __half a1 = __float2half_rn(ra), b1v = __float2half_rn(rb);
            p0[i>>1] = (unsigned int)__half_as_ushort(a0) |
                       ((unsigned int)__half_as_ushort(b0) << 16);
            p1[i>>1] = (unsigned int)__half_as_ushort(a1) |
                       ((unsigned int)__half_as_ushort(b1v) << 16);
        }
        size_t off = (size_t)gr*DD + c0;
        *(uint4*)(g_x0 + off) = make_uint4(p0[0],p0[1],p0[2],p0[3]);
        *(uint4*)(g_x1 + off) = make_uint4(p1[0],p1[1],p1[2],p1[3]);
    }
    #pragma unroll
    for (int i = 0; i < 8; i++) wacc[w*DD + c0 + i] = acc[i];
    __syncthreads();
    float s = 0.f;
    #pragma unroll
    for (int ww = 0; ww < 8; ww++) s += wacc[ww*DD + tid];
    g_frp[(size_t)blockIdx.x*DD + tid] = s;
}

// ---------------------------------------------------------------------------
// K_mma (R8 known-good, FROZEN — 3 restructure attempts all regressed):
// fp16 3-pass split GEMM (hi*hi, hi*lo, lo*hi) via mma.sync.
// Block 128M x 352N, 512 threads = 16 warps (4m x 4n), warp tile 32x88.
// 3-buffer cp.async pipeline (2 stages in flight, ONE sync per stage).
// ---------------------------------------------------------------------------
#define ABUF 16384
#define BBUF 45056
#define OFF_B0 (3*ABUF)
#define OFF_SC (OFF_B0 + 3*BBUF)
#define MMA_SMEM (OFF_SC + 2048)

__global__ __launch_bounds__(512, 1) void k_mma(const float* __restrict__ b2) {
    extern __shared__ char smem[];
    uint32_t sb = smem_u32(smem);
    int tid = threadIdx.x, lane = tid & 31, wid = tid >> 5;
    int warp_m = wid & 3, warp_n = wid >> 2;
    int row0 = blockIdx.x * 128;

    int sub = lane >> 3, rr = lane & 7;
    uint32_t a_sw[2];
    #pragma unroll
    for (int mt = 0; mt < 2; mt++) {
        int rowA = warp_m*32 + mt*16 + (sub & 1)*8 + rr;
        a_sw[mt] = (uint32_t)(rowA*128 + (((sub >> 1)*16) ^ ((rowA & 7)*16)));
    }
    uint32_t b_sw[6];
    #pragma unroll
    for (int np = 0; np < 5; np++) {
        int rowB = warp_n*88 + np*16 + ((lane >> 3) & 1)*8 + (lane & 7);
        b_sw[np] = (uint32_t)(rowB*128 + (((lane >> 4)*16) ^ ((rowB & 7)*16)));
    }
    {
        int l = lane & 15;
        int rowB = warp_n*88 + 80 + (l & 7);
        b_sw[5] = (uint32_t)(rowB*128 + (((l >> 3)*16) ^ ((rowB & 7)*16)));
    }

    float acc[2][11][4];
    #pragma unroll
    for (int mt = 0; mt < 2; mt++)
        #pragma unroll
        for (int nt = 0; nt < 11; nt++)
            #pragma unroll
            for (int q = 0; q < 4; q++) acc[mt][nt][q] = 0.f;

    auto issue = [&](int s, uint32_t abase, uint32_t bbase) {
        int p = s >> 2, kc = s & 3;
        const __half* asrc = (p == 2) ? g_x1 : g_x0;
        const __half* bsrc = (p == 1) ? g_w1t : g_w0t;
        #pragma unroll
        for (int it = 0; it < 2; it++) {
            int v = it*512 + tid;
            int r = v >> 3, cv = v & 7;
            cp16(abase + SWZ128((uint32_t)(r*128 + cv*16)),
                 asrc + (size_t)(row0 + r)*DD + kc*64 + cv*8);
        }
        #pragma unroll
        for (int it = 0; it < 6; it++) {
            int v = it*512 + tid;
            if (v < 2816) {
                int r = v >> 3, cv = v & 7;
                cp16(bbase + SWZ128((uint32_t)(r*128 + cv*16)),
                     bsrc + (size_t)r*DD + kc*64 + cv*8);
            }
        }
        CP_COMMIT();
    };

    auto compute = [&](uint32_t ab, uint32_t bb) {
        #pragma unroll
        for (int ks = 0; ks < 4; ks++) {
            const uint32_t kx = (uint32_t)(ks*32);
            uint32_t afr[2][4];
            #pragma unroll
            for (int mt = 0; mt < 2; mt++)
                ldsm_x4(afr[mt][0], afr[mt][1], afr[mt][2], afr[mt][3],
                        ab + (a_sw[mt] ^ kx));
            #pragma unroll
            for (int np = 0; np < 5; np++) {
                uint32_t b0a, b1a, b0b, b1b;
                ldsm_x4(b0a, b1a, b0b, b1b, bb + (b_sw[np] ^ kx));
                uint32_t be[2] = {b0a, b0b};
                uint32_t bo[2] = {b1a, b1b};
                mma16816(acc[0][2*np],   afr[0], be);
                mma16816(acc[1][2*np],   afr[1], be);
                mma16816(acc[0][2*np+1], afr[0], bo);
                mma16816(acc[1][2*np+1], afr[1], bo);
            }
            {
                uint32_t b0, b1;
                ldsm_x2(b0, b1, bb + (b_sw[5] ^ kx));
                uint32_t bfr[2] = {b0, b1};
                mma16816(acc[0][10], afr[0], bfr);
                mma16816(acc[1][10], afr[1], bfr);
            }
        }
    };

    issue(0, sb + 0*ABUF, sb + OFF_B0 + 0*BBUF);
    issue(1, sb + 1*ABUF, sb + OFF_B0 + 1*BBUF);
    for (int u = 0; u < 4; u++) {
        CP_WAIT(1); __syncthreads();
        issue(3*u + 2, sb + 2*ABUF, sb + OFF_B0 + 2*BBUF);
        compute(sb + 0*ABUF, sb + OFF_B0 + 0*BBUF);
        CP_WAIT(1); __syncthreads();
        if (u < 3) issue(3*u + 3, sb + 0*ABUF, sb + OFF_B0 + 0*BBUF);
        compute(sb + 1*ABUF, sb + OFF_B0 + 1*BBUF);
        if (u < 3) { CP_WAIT(1); __syncthreads(); }
        else       { CP_WAIT(0); __syncthreads(); }
        if (u < 3) issue(3*u + 4, sb + 1*ABUF, sb + OFF_B0 + 1*BBUF);
        compute(sb + 2*ABUF, sb + OFF_B0 + 2*BBUF);
    }
    __syncthreads();

    int g = lane >> 2, ti = lane & 3;
    float* scb = (float*)(smem + OFF_SC);
    #pragma unroll
    for (int mt = 0; mt < 2; mt++) {
        float s0 = 0.f, s1 = 0.f;
        #pragma unroll
        for (int nt = 0; nt < 11; nt++) {
            int ng = warp_n*88 + nt*8 + ti*2;
            float w2a = g_w2p[ng],   b1a = g_b1p[ng];
            float w2b = g_w2p[ng+1], b1b = g_b1p[ng+1];
            s0 += w2a*gelu_exact(acc[mt][nt][0] + b1a) +
                  w2b*gelu_exact(acc[mt][nt][1] + b1b);
            s1 += w2a*gelu_exact(acc[mt][nt][2] + b1a) +
                  w2b*gelu_exact(acc[mt][nt][3] + b1b);
        }
        s0 += __shfl_xor_sync(0xffffffffu, s0, 1);
        s0 += __shfl_xor_sync(0xffffffffu, s0, 2);
        s1 += __shfl_xor_sync(0xffffffffu, s1, 1);
        s1 += __shfl_xor_sync(0xffffffffu, s1, 2);
        if (ti == 0) {
            scb[warp_n*128 + warp_m*32 + mt*16 + g]     = s0;
            scb[warp_n*128 + warp_m*32 + mt*16 + g + 8] = s1;
        }
    }
    __syncthreads();
    if (tid < 128)
        g_scores[row0 + tid] = scb[tid] + scb[128 + tid] + scb[256 + tid] +
                               scb[384 + tid] + __ldg(b2);
}

// ---------------------------------------------------------------------------
// K_sortrank: bitonic sort of (mapped_score, idx) keys per batch; sorted
// position == counting-based pos (keys unique). Produces hard/seg/g_st,
// den, rho_eff in ONE kernel (replaces rank1 + rank2). grid 32, 1024 thr.
// ---------------------------------------------------------------------------
__device__ __forceinline__ unsigned long long rank_key(float a, float sc, int idx) {
    unsigned int u;
    if (a == 0.f) u = 0xFFFFFFFFu;
    else {
        u = __float_as_uint(sc);
        u = (u & 0x80000000u) ? ~u : (u | 0x80000000u);
    }
    return ((unsigned long long)u << 10) | (unsigned int)idx;
}

__global__ void k_sortrank(const float* __restrict__ attn, float* __restrict__ out) {
    __shared__ unsigned long long sk[TT];
    __shared__ float aS[TT];
    __shared__ float red[32];
    __shared__ float red8[32*8];
    __shared__ float teff_s;
    int b = blockIdx.x, t = threadIdx.x;
    int lane = t & 31, w = t >> 5;

    float a = attn[b*TT + t];
    aS[t] = a;
    sk[t] = rank_key(a, g_scores[b*TT + t], t);
    float Teff = blockReduce1024(a, red);   // syncs inside make sk/aS visible
    if (t == 0) teff_s = Teff;

    // ---- bitonic sort ascending (keys unique -> deterministic) ----
    #pragma unroll 1
    for (int ksz = 2; ksz <= TT; ksz <<= 1) {
        #pragma unroll 1
        for (int j = ksz >> 1; j > 0; j >>= 1) {
            int ixj = t ^ j;
            if (ixj > t) {
                bool asc = ((t & ksz) == 0);
                unsigned long long x = sk[t], y = sk[ixj];
                if ((x > y) == asc) { sk[t] = y; sk[ixj] = x; }
            }
            __syncthreads();
        }
    }

    // thread t owns the t-th smallest key; pos == t
    unsigned long long key = sk[t];
    int idx = (int)(key & 1023u);
    float av = aS[idx];
    Teff = teff_s;
    float posf = (float)t;

    float hard[RRR];
    int seg = RRR;
    #pragma unroll
    for (int r = RRR-1; r >= 0; r--) {
        float kk = rintf(c_rho[r]*Teff);
        kk = (Teff > 0.f) ? fmaxf(kk, 1.f) : 0.f;
        hard[r] = (posf < kk) ? 1.f : 0.f;
        if (hard[r] > 0.f) seg = r;
    }
    g_seg[b*TT + idx] = seg;
    out[b*TT + idx] = hard[RRR-1];
    #pragma unroll
    for (int r = 0; r < RRR; r++)
        out[HARD_OFF + (r*BB + b)*TT + idx] = hard[r];

    float v[8];
    #pragma unroll
    for (int r = 0; r < RRR; r++) { v[r] = av*hard[r]; v[4+r] = hard[r]; }
    #pragma unroll
    for (int j = 0; j < 8; j++)
        #pragma unroll
        for (int o = 16; o; o >>= 1) v[j] += __shfl_xor_sync(0xffffffffu, v[j], o);
    if (lane == 0)
        #pragma unroll
        for (int j = 0; j < 8; j++) red8[w*8 + j] = v[j];
    __syncthreads();
    if (t < 8) {
        float s = 0.f;
        for (int ww = 0; ww < 32; ww++) s += red8[ww*8 + t];
        if (t < 4) g_den[t*BB + b] = s;
        else out[RHOE_OFF + (t-4)*BB + b] = s / fmaxf(teff_s, 1.f);
    }
}

// ---------------------------------------------------------------------------
// K_predpart: nested-mask pooling partials. grid (32, NSP=32), 256 threads.
// ---------------------------------------------------------------------------
__global__ void k_predpart(const float* __restrict__ attn,
                           const int* __restrict__ ids,
                           const float* __restrict__ table) {
    const int TS = TT/NSP;   // 32
    __shared__ float wS[TS];
    __shared__ int   sS[TS];
    __shared__ int   iS[TS];
    int b = blockIdx.x, sp = blockIdx.y, d = threadIdx.x;
    if (d < TS) {
        int t = sp*TS + d;
        int sg = g_seg[b*TT + t];
        sS[d] = sg;
        wS[d] = (sg < 4) ? attn[b*TT + t] : 0.f;
        iS[d] = ids[b*TT + t];
    }
    __syncthreads();
    float s0=0.f, s1=0.f, s2=0.f, s3=0.f;
    #pragma unroll
    for (int t0 = 0; t0 < TS; t0 += 8) {
        float v[8], ww[8]; int sg[8];
        #pragma unroll
        for (int u = 0; u < 8; u++) {
            sg[u] = sS[t0+u]; ww[u] = wS[t0+u];
            v[u] = __ldg(&table[(size_t)iS[t0+u]*DD + d]);
        }
        #pragma unroll
        for (int u = 0; u < 8; u++) {
            float wv = ww[u]*v[u];
            s0 += (sg[u]==0)?wv:0.f; s1 += (sg[u]==1)?wv:0.f;
            s2 += (sg[u]==2)?wv:0.f; s3 += (sg[u]==3)?wv:0.f;
        }
    }
    float* pp = g_pp + ((size_t)(b*NSP + sp)*RRR)*DD + d;
    pp[0*DD]=s0; pp[1*DD]=s1; pp[2*DD]=s2; pp[3*DD]=s3;
}

// ---------------------------------------------------------------------------
// K_predred: fullrep reduce + norm + nested prefix + cosine; last block
// also computes recon_avg and per-rho means. grid 32, 256 threads.
// ---------------------------------------------------------------------------
__global__ void k_predred(const float* __restrict__ attn, float* __restrict__ out) {
    __shared__ float red[32];
    __shared__ int last_s;
    int b = blockIdx.x, d = threadIdx.x;

    float a = 0.f;
    #pragma unroll
    for (int i = 0; i < 4; i++) a += attn[b*TT + d + 256*i];
    float den = blockReduce256(a, red);
    float fr = 0.f;
    #pragma unroll
    for (int q = 0; q < NFQ; q++) fr += g_frp[(b*NFQ + q)*DD + d];
    fr /= fmaxf(den, 1e-8f);
    float sq0 = blockReduce256(fr*fr, red);
    float nf = fmaxf(sqrtf(sq0), 1e-8f);

    float s0=0.f, s1=0.f, s2=0.f, s3=0.f;
    #pragma unroll
    for (int sp = 0; sp < NSP; sp++) {
        const float* pp = g_pp + ((size_t)(b*NSP + sp)*RRR)*DD + d;
        s0 += pp[0*DD]; s1 += pp[1*DD]; s2 += pp[2*DD]; s3 += pp[3*DD];
    }
    s1 += s0; s2 += s1; s3 += s2;
    float ss[4] = {s0, s1, s2, s3};
    #pragma unroll
    for (int r = 0; r < RRR; r++) {
        float pred = ss[r] / fmaxf(g_den[r*BB + b], 1e-8f);
        float dot = blockReduce256(pred*fr, red);
        float sq  = blockReduce256(pred*pred, red);
        if (d == 0)
            g_ps[r*BB + b] = 1.f - dot/(fmaxf(sqrtf(sq), 1e-8f)*nf);
    }

    if (d == 0) {
        __threadfence();
        int v = atomicAdd(&g_ctr, 1);
        last_s = (v == BB - 1);
    }
    __syncthreads();
    if (last_s) {
        __threadfence();
        if (d == 0) {
            float s = 0.f;
            for (int i = 0; i < RRR*BB; i++) s += g_ps[i];
            out[SCAL_OFF] = s * (1.f/(RRR*BB));
            g_ctr = 0;   // reset for next graph replay
        }
        if (d >= 1 && d <= RRR) {
            int r = d - 1;
            float s = 0.f;
            for (int bb = 0; bb < BB; bb++) s += g_ps[r*BB + bb];
            out[PSM_OFF + r] = s * (1.f/BB);
        }
    }
}

// ---------------------------------------------------------------------------
extern "C" void kernel_launch(void* const* d_in, const int* in_sizes, int n_in,
                              void* d_out, int out_size) {
    const int*   ids  = (const int*)  d_in[0];
    const float* emb  = (const float*)d_in[1];
    const float* attn = (const float*)d_in[2];
    const float* lnw  = (const float*)d_in[3];
    const float* lnb  = (const float*)d_in[4];
    const float* w1   = (const float*)d_in[5];
    const float* b1   = (const float*)d_in[6];
    const float* w2   = (const float*)d_in[7];
    const float* b2   = (const float*)d_in[8];
    const float* tbl  = (const float*)d_in[9];
    float* out = (float*)d_out;

    cudaFuncSetAttribute(k_mma, cudaFuncAttributeMaxDynamicSharedMemorySize,
                         MMA_SMEM);

    k_split<<<512 + NPAD, 256>>>(emb, attn, lnw, lnb, w1, b1, w2);
    k_mma<<<NROWS/128, 512, MMA_SMEM>>>(b2);
    k_sortrank<<<BB, TT>>>(attn, out);
    k_predpart<<<dim3(BB, NSP), 256>>>(attn, ids, tbl);
    k_predred<<<BB, 256>>>(attn, out);
}

// round 15
// speedup vs baseline: 1.0545x; 1.0545x over previous
#include <cuda_runtime.h>
#include <cuda_fp16.h>
#include <math.h>
#include <stdint.h>

#define BB 32
#define TT 1024
#define DD 256
#define HH 341
#define RRR 4
#define NSP 32
#define NFQ 16
#define NPAD 352        // H padded to 352
#define NROWS (BB*TT)   // 32768

// Output layout
#define HARD_OFF  (BB*TT)
#define SCAL_OFF  (HARD_OFF + RRR*BB*TT)
#define PSM_OFF   (SCAL_OFF + 1)
#define RHOE_OFF  (PSM_OFF + RRR)

// Device scratch
__device__ __half g_x0[NROWS*DD];      // fp16 hi of LN output
__device__ __half g_x1[NROWS*DD];      // fp16 residual
__device__ __half g_w0t[NPAD*DD];      // [n][k] transposed w1 hi
__device__ __half g_w1t[NPAD*DD];      // [n][k] transposed w1 residual
__device__ float g_b1p[NPAD];
__device__ float g_w2p[NPAD];
__device__ float g_scores[BB*TT];
__device__ float g_frp[BB*NFQ*DD];
__device__ int   g_seg[BB*TT];
__device__ float g_den[RRR*BB];
__device__ float g_ps[RRR*BB];
__device__ float g_pp[BB*NSP*RRR*DD];
__device__ unsigned int g_posp[8*BB*TT];
__device__ int   g_ctr;                // last-block counter (reset each run)

__constant__ float c_rho[RRR] = {0.1f, 0.25f, 0.5f, 0.75f};

#define SWZ128(x) ((x) ^ (((x) >> 3) & 0x70))

__device__ __forceinline__ uint32_t smem_u32(const void* p) {
    uint32_t a;
    asm("{ .reg .u64 t; cvta.to.shared.u64 t, %1; cvt.u32.u64 %0, t; }"
        : "=r"(a) : "l"(p));
    return a;
}
__device__ __forceinline__ void cp16(uint32_t dst, const void* src) {
    asm volatile("cp.async.cg.shared.global [%0], [%1], 16;"
                 :: "r"(dst), "l"(src));
}
#define CP_COMMIT() asm volatile("cp.async.commit_group;" ::: "memory")
#define CP_WAIT(n)  asm volatile("cp.async.wait_group %0;" :: "n"(n) : "memory")

__device__ __forceinline__ void ldsm_x4(uint32_t& r0, uint32_t& r1,
                                        uint32_t& r2, uint32_t& r3, uint32_t a) {
    asm volatile("ldmatrix.sync.aligned.m8n8.x4.shared.b16 {%0,%1,%2,%3}, [%4];"
                 : "=r"(r0), "=r"(r1), "=r"(r2), "=r"(r3) : "r"(a));
}
__device__ __forceinline__ void ldsm_x2(uint32_t& r0, uint32_t& r1, uint32_t a) {
    asm volatile("ldmatrix.sync.aligned.m8n8.x2.shared.b16 {%0,%1}, [%2];"
                 : "=r"(r0), "=r"(r1) : "r"(a));
}
__device__ __forceinline__ void mma16816(float* c, const uint32_t* a,
                                         const uint32_t* b) {
    asm volatile("mma.sync.aligned.m16n8k16.row.col.f32.f16.f16.f32 "
                 "{%0,%1,%2,%3}, {%4,%5,%6,%7}, {%8,%9}, {%0,%1,%2,%3};"
                 : "+f"(c[0]), "+f"(c[1]), "+f"(c[2]), "+f"(c[3])
                 : "r"(a[0]), "r"(a[1]), "r"(a[2]), "r"(a[3]),
                   "r"(b[0]), "r"(b[1]));
}
__device__ __forceinline__ float gelu_exact(float x) {
    return 0.5f * x * (1.f + erff(x * 0.7071067811865476f));
}

// ---------------------------------------------------------------------------
// Reductions
// ---------------------------------------------------------------------------
__device__ __forceinline__ float blockReduce1024(float v, float* red) {
    int lane = threadIdx.x & 31, w = threadIdx.x >> 5;
    #pragma unroll
    for (int o = 16; o; o >>= 1) v += __shfl_xor_sync(0xffffffffu, v, o);
    __syncthreads();
    if (lane == 0) red[w] = v;
    __syncthreads();
    if (w == 0) {
        float s = red[lane];
        #pragma unroll
        for (int o = 16; o; o >>= 1) s += __shfl_xor_sync(0xffffffffu, s, o);
        if (lane == 0) red[0] = s;
    }
    __syncthreads();
    return red[0];
}
__device__ __forceinline__ float blockReduce256(float v, float* red) {
    int lane = threadIdx.x & 31, w = threadIdx.x >> 5;
    #pragma unroll
    for (int o = 16; o; o >>= 1) v += __shfl_xor_sync(0xffffffffu, v, o);
    __syncthreads();
    if (lane == 0) red[w] = v;
    __syncthreads();
    if (w == 0) {
        float s = (lane < 8) ? red[lane] : 0.f;
        #pragma unroll
        for (int o = 16; o; o >>= 1) s += __shfl_xor_sync(0xffffffffu, s, o);
        if (lane == 0) red[0] = s;
    }
    __syncthreads();
    return red[0];
}

// ---------------------------------------------------------------------------
// K_split (fused with wsplit): blocks [0,512) do LN+fp16x2 split + fullrep
// partials; blocks [512, 512+NPAD) transpose+pad+split w1 and pad b1/w2.
// ---------------------------------------------------------------------------
__global__ __launch_bounds__(256) void k_split(const float* __restrict__ emb,
                                               const float* __restrict__ attn,
                                               const float* __restrict__ lnw,
                                               const float* __restrict__ lnb,
                                               const float* __restrict__ w1,
                                               const float* __restrict__ b1,
                                               const float* __restrict__ w2) {
    __shared__ float wacc[8*DD];
    int tid = threadIdx.x;
    if (blockIdx.x >= 512) {
        int n = blockIdx.x - 512, k = tid;
        float v = (n < HH) ? w1[(size_t)k*HH + n] : 0.f;
        __half h0 = __float2half_rn(v);
        float r = v - __half2float(h0);
        __half h1 = __float2half_rn(r);
        g_w0t[n*DD + k] = h0;
        g_w1t[n*DD + k] = h1;
        if (k == 0) {
            g_b1p[n] = (n < HH) ? b1[n] : 0.f;
            g_w2p[n] = (n < HH) ? w2[n] : 0.f;
        }
        return;
    }
    int lane = tid & 31, w = tid >> 5;
    int row0 = blockIdx.x * 64;
    int c0 = lane * 8;
    float lw[8], lb[8];
    #pragma unroll
    for (int i = 0; i < 8; i++) { lw[i] = lnw[c0+i]; lb[i] = lnb[c0+i]; }

    float acc[8] = {0,0,0,0,0,0,0,0};
    for (int rr = 0; rr < 8; rr++) {
        int gr = row0 + w*8 + rr;
        float sel = attn[gr];
        const float4* ep = (const float4*)(emb + (size_t)gr*DD + c0);
        float4 e0 = ep[0], e1 = ep[1];
        float e[8] = {e0.x,e0.y,e0.z,e0.w,e1.x,e1.y,e1.z,e1.w};
        #pragma unroll
        for (int i = 0; i < 8; i++) acc[i] += sel * e[i];
        float x[8]; float s = 0.f;
        #pragma unroll
        for (int i = 0; i < 8; i++) { x[i] = e[i]*sel; s += x[i]; }
        #pragma unroll
        for (int o = 16; o; o >>= 1) s += __shfl_xor_sync(0xffffffffu, s, o);
        float mean = s * (1.f/256.f);
        float v = 0.f;
        #pragma unroll
        for (int i = 0; i < 8; i++) { float dl = x[i]-mean; v += dl*dl; }
        #pragma unroll
        for (int o = 16; o; o >>= 1) v += __shfl_xor_sync(0xffffffffu, v, o);
        float rstd = rsqrtf(v*(1.f/256.f) + 1e-5f);
        unsigned int p0[4], p1[4];
        #pragma unroll
        for (int i = 0; i < 8; i += 2) {
            float ya = (x[i]-mean)*rstd*lw[i] + lb[i];
            float yb = (x[i+1]-mean)*rstd*lw[i+1] + lb[i+1];
            __half a0 = __float2half_rn(ya), b0 = __float2half_rn(yb);
            float ra = ya - __half2float(a0), rb = yb - __half2float(b0);
            __half a1 = __float2half_rn(ra), b1v = __float2half_rn(rb);
            p0[i>>1] = (unsigned int)__half_as_ushort(a0) |
                       ((unsigned int)__half_as_ushort(b0) << 16);
            p1[i>>1] = (unsigned int)__half_as_ushort(a1) |
                       ((unsigned int)__half_as_ushort(b1v) << 16);
        }
        size_t off = (size_t)gr*DD + c0;
        *(uint4*)(g_x0 + off) = make_uint4(p0[0],p0[1],p0[2],p0[3]);
        *(uint4*)(g_x1 + off) = make_uint4(p1[0],p1[1],p1[2],p1[3]);
    }
    #pragma unroll
    for (int i = 0; i < 8; i++) wacc[w*DD + c0 + i] = acc[i];
    __syncthreads();
    float s = 0.f;
    #pragma unroll
    for (int ww = 0; ww < 8; ww++) s += wacc[ww*DD + tid];
    g_frp[(size_t)blockIdx.x*DD + tid] = s;
}

// ---------------------------------------------------------------------------
// K_mma (R8 known-good, FROZEN): fp16 3-pass split GEMM via mma.sync.
// Block 128M x 352N, 512 threads = 16 warps (4m x 4n), warp tile 32x88.
// 3-buffer cp.async pipeline (2 stages in flight, ONE sync per stage).
// ---------------------------------------------------------------------------
#define ABUF 16384
#define BBUF 45056
#define OFF_B0 (3*ABUF)
#define OFF_SC (OFF_B0 + 3*BBUF)
#define MMA_SMEM (OFF_SC + 2048)

__global__ __launch_bounds__(512, 1) void k_mma(const float* __restrict__ b2) {
    extern __shared__ char smem[];
    uint32_t sb = smem_u32(smem);
    int tid = threadIdx.x, lane = tid & 31, wid = tid >> 5;
    int warp_m = wid & 3, warp_n = wid >> 2;
    int row0 = blockIdx.x * 128;

    int sub = lane >> 3, rr = lane & 7;
    uint32_t a_sw[2];
    #pragma unroll
    for (int mt = 0; mt < 2; mt++) {
        int rowA = warp_m*32 + mt*16 + (sub & 1)*8 + rr;
        a_sw[mt] = (uint32_t)(rowA*128 + (((sub >> 1)*16) ^ ((rowA & 7)*16)));
    }
    uint32_t b_sw[6];
    #pragma unroll
    for (int np = 0; np < 5; np++) {
        int rowB = warp_n*88 + np*16 + ((lane >> 3) & 1)*8 + (lane & 7);
        b_sw[np] = (uint32_t)(rowB*128 + (((lane >> 4)*16) ^ ((rowB & 7)*16)));
    }
    {
        int l = lane & 15;
        int rowB = warp_n*88 + 80 + (l & 7);
        b_sw[5] = (uint32_t)(rowB*128 + (((l >> 3)*16) ^ ((rowB & 7)*16)));
    }

    float acc[2][11][4];
    #pragma unroll
    for (int mt = 0; mt < 2; mt++)
        #pragma unroll
        for (int nt = 0; nt < 11; nt++)
            #pragma unroll
            for (int q = 0; q < 4; q++) acc[mt][nt][q] = 0.f;

    auto issue = [&](int s, uint32_t abase, uint32_t bbase) {
        int p = s >> 2, kc = s & 3;
        const __half* asrc = (p == 2) ? g_x1 : g_x0;
        const __half* bsrc = (p == 1) ? g_w1t : g_w0t;
        #pragma unroll
        for (int it = 0; it < 2; it++) {
            int v = it*512 + tid;
            int r = v >> 3, cv = v & 7;
            cp16(abase + SWZ128((uint32_t)(r*128 + cv*16)),
                 asrc + (size_t)(row0 + r)*DD + kc*64 + cv*8);
        }
        #pragma unroll
        for (int it = 0; it < 6; it++) {
            int v = it*512 + tid;
            if (v < 2816) {
                int r = v >> 3, cv = v & 7;
                cp16(bbase + SWZ128((uint32_t)(r*128 + cv*16)),
                     bsrc + (size_t)r*DD + kc*64 + cv*8);
            }
        }
        CP_COMMIT();
    };

    auto compute = [&](uint32_t ab, uint32_t bb) {
        #pragma unroll
        for (int ks = 0; ks < 4; ks++) {
            const uint32_t kx = (uint32_t)(ks*32);
            uint32_t afr[2][4];
            #pragma unroll
            for (int mt = 0; mt < 2; mt++)
                ldsm_x4(afr[mt][0], afr[mt][1], afr[mt][2], afr[mt][3],
                        ab + (a_sw[mt] ^ kx));
            #pragma unroll
            for (int np = 0; np < 5; np++) {
                uint32_t b0a, b1a, b0b, b1b;
                ldsm_x4(b0a, b1a, b0b, b1b, bb + (b_sw[np] ^ kx));
                uint32_t be[2] = {b0a, b0b};
                uint32_t bo[2] = {b1a, b1b};
                mma16816(acc[0][2*np],   afr[0], be);
                mma16816(acc[1][2*np],   afr[1], be);
                mma16816(acc[0][2*np+1], afr[0], bo);
                mma16816(acc[1][2*np+1], afr[1], bo);
            }
            {
                uint32_t b0, b1;
                ldsm_x2(b0, b1, bb + (b_sw[5] ^ kx));
                uint32_t bfr[2] = {b0, b1};
                mma16816(acc[0][10], afr[0], bfr);
                mma16816(acc[1][10], afr[1], bfr);
            }
        }
    };

    issue(0, sb + 0*ABUF, sb + OFF_B0 + 0*BBUF);
    issue(1, sb + 1*ABUF, sb + OFF_B0 + 1*BBUF);
    for (int u = 0; u < 4; u++) {
        CP_WAIT(1); __syncthreads();
        issue(3*u + 2, sb + 2*ABUF, sb + OFF_B0 + 2*BBUF);
        compute(sb + 0*ABUF, sb + OFF_B0 + 0*BBUF);
        CP_WAIT(1); __syncthreads();
        if (u < 3) issue(3*u + 3, sb + 0*ABUF, sb + OFF_B0 + 0*BBUF);
        compute(sb + 1*ABUF, sb + OFF_B0 + 1*BBUF);
        if (u < 3) { CP_WAIT(1); __syncthreads(); }
        else       { CP_WAIT(0); __syncthreads(); }
        if (u < 3) issue(3*u + 4, sb + 1*ABUF, sb + OFF_B0 + 1*BBUF);
        compute(sb + 2*ABUF, sb + OFF_B0 + 2*BBUF);
    }
    __syncthreads();

    int g = lane >> 2, ti = lane & 3;
    float* scb = (float*)(smem + OFF_SC);
    #pragma unroll
    for (int mt = 0; mt < 2; mt++) {
        float s0 = 0.f, s1 = 0.f;
        #pragma unroll
        for (int nt = 0; nt < 11; nt++) {
            int ng = warp_n*88 + nt*8 + ti*2;
            float w2a = g_w2p[ng],   b1a = g_b1p[ng];
            float w2b = g_w2p[ng+1], b1b = g_b1p[ng+1];
            s0 += w2a*gelu_exact(acc[mt][nt][0] + b1a) +
                  w2b*gelu_exact(acc[mt][nt][1] + b1b);
            s1 += w2a*gelu_exact(acc[mt][nt][2] + b1a) +
                  w2b*gelu_exact(acc[mt][nt][3] + b1b);
        }
        s0 += __shfl_xor_sync(0xffffffffu, s0, 1);
        s0 += __shfl_xor_sync(0xffffffffu, s0, 2);
        s1 += __shfl_xor_sync(0xffffffffu, s1, 1);
        s1 += __shfl_xor_sync(0xffffffffu, s1, 2);
        if (ti == 0) {
            scb[warp_n*128 + warp_m*32 + mt*16 + g]     = s0;
            scb[warp_n*128 + warp_m*32 + mt*16 + g + 8] = s1;
        }
    }
    __syncthreads();
    if (tid < 128)
        g_scores[row0 + tid] = scb[tid] + scb[128 + tid] + scb[256 + tid] +
                               scb[384 + tid] + __ldg(b2);
}

// ---------------------------------------------------------------------------
// K_rank1: partial rank-position counts. grid (32, 8), 1024 threads.
// ---------------------------------------------------------------------------
__device__ __forceinline__ unsigned long long rank_key(float a, float sc, int idx) {
    unsigned int u;
    if (a == 0.f) u = 0xFFFFFFFFu;
    else {
        u = __float_as_uint(sc);
        u = (u & 0x80000000u) ? ~u : (u | 0x80000000u);
    }
    return ((unsigned long long)u << 10) | (unsigned int)idx;
}

__global__ void k_rank1(const float* __restrict__ attn) {
    __shared__ unsigned long long ck[128];
    int b = blockIdx.x, c = blockIdx.y, t = threadIdx.x;
    if (t < 128) {
        int i = c*128 + t;
        ck[t] = rank_key(attn[b*TT + i], g_scores[b*TT + i], i);
    }
    __syncthreads();
    unsigned long long pt = rank_key(attn[b*TT + t], g_scores[b*TT + t], t);
    int cnt = 0;
    #pragma unroll 8
    for (int j = 0; j < 128; j++) cnt += (ck[j] < pt) ? 1 : 0;
    g_posp[c*(BB*TT) + b*TT + t] = (unsigned int)cnt;
}

// K_rank2: combine counts, hard/seg/outputs. grid 32, 1024 threads.
__global__ void k_rank2(const float* __restrict__ attn, float* __restrict__ out) {
    __shared__ float red[32];
    __shared__ float red8[32*8];
    __shared__ float teff_s;
    int b = blockIdx.x, t = threadIdx.x;
    int lane = t & 31, w = t >> 5;
    float a = attn[b*TT + t];
    unsigned int pos = 0;
    #pragma unroll
    for (int c = 0; c < 8; c++) pos += g_posp[c*(BB*TT) + b*TT + t];
    float Teff = blockReduce1024(a, red);
    if (t == 0) teff_s = Teff;
    float posf = (float)pos;

    float hard[RRR];
    int seg = RRR;
    #pragma unroll
    for (int r = RRR-1; r >= 0; r--) {
        float kk = rintf(c_rho[r]*Teff);
        kk = (Teff > 0.f) ? fmaxf(kk, 1.f) : 0.f;
        hard[r] = (posf < kk) ? 1.f : 0.f;
        if (hard[r] > 0.f) seg = r;
    }
    g_seg[b*TT + t] = seg;
    out[b*TT + t] = hard[RRR-1];
    #pragma unroll
    for (int r = 0; r < RRR; r++)
        out[HARD_OFF + (r*BB + b)*TT + t] = hard[r];

    float v[8];
    #pragma unroll
    for (int r = 0; r < RRR; r++) { v[r] = a*hard[r]; v[4+r] = hard[r]; }
    #pragma unroll
    for (int j = 0; j < 8; j++)
        #pragma unroll
        for (int o = 16; o; o >>= 1) v[j] += __shfl_xor_sync(0xffffffffu, v[j], o);
    if (lane == 0)
        #pragma unroll
        for (int j = 0; j < 8; j++) red8[w*8 + j] = v[j];
    __syncthreads();
    if (t < 8) {
        float s = 0.f;
        for (int ww = 0; ww < 32; ww++) s += red8[ww*8 + t];
        if (t < 4) g_den[t*BB + b] = s;
        else out[RHOE_OFF + (t-4)*BB + b] = s / fmaxf(teff_s, 1.f);
    }
}

// ---------------------------------------------------------------------------
// K_predpart (v2): float4 gathers, warp-uniform segment branch, seg-4 skip.
// grid (32, NSP=32), 256 threads = 64 dim-groups x 4 token-subsets.
// Each thread: 8 tokens x float4 (4 dims). Subset partials combined in smem.
// ---------------------------------------------------------------------------
__global__ __launch_bounds__(256) void k_predpart(const float* __restrict__ attn,
                                                  const int* __restrict__ ids,
                                                  const float* __restrict__ table) {
    const int TS = TT/NSP;   // 32 tokens per block
    __shared__ float wS[TS];
    __shared__ int   sS[TS];
    __shared__ int   iS[TS];
    __shared__ float part[4][RRR][DD];   // [subset][seg][dim] = 16 KB
    int b = blockIdx.x, sp = blockIdx.y, tid = threadIdx.x;
    if (tid < TS) {
        int t = sp*TS + tid;
        int sg = g_seg[b*TT + t];
        sS[tid] = sg;
        wS[tid] = (sg < 4) ? attn[b*TT + t] : 0.f;
        iS[tid] = ids[b*TT + t];
    }
    __syncthreads();

    int dg = tid & 63, sub = tid >> 6;   // dim-group (4 dims), token-subset
    float4 a0 = {0,0,0,0}, a1 = {0,0,0,0}, a2 = {0,0,0,0}, a3 = {0,0,0,0};
    #pragma unroll
    for (int u = 0; u < 8; u++) {
        int t = sub*8 + u;
        int sg = sS[t];                  // warp-uniform (all lanes same t)
        if (sg < 4) {
            float w = wS[t];
            float4 v = __ldg((const float4*)(table + (size_t)iS[t]*DD) + dg);
            float4 wv = make_float4(w*v.x, w*v.y, w*v.z, w*v.w);
            if (sg == 0)      { a0.x += wv.x; a0.y += wv.y; a0.z += wv.z; a0.w += wv.w; }
            else if (sg == 1) { a1.x += wv.x; a1.y += wv.y; a1.z += wv.z; a1.w += wv.w; }
            else if (sg == 2) { a2.x += wv.x; a2.y += wv.y; a2.z += wv.z; a2.w += wv.w; }
            else              { a3.x += wv.x; a3.y += wv.y; a3.z += wv.z; a3.w += wv.w; }
        }
    }
    *(float4*)&part[sub][0][dg*4] = a0;
    *(float4*)&part[sub][1][dg*4] = a1;
    *(float4*)&part[sub][2][dg*4] = a2;
    *(float4*)&part[sub][3][dg*4] = a3;
    __syncthreads();

    // combine 4 subsets; thread tid owns dim tid
    float* pp = g_pp + ((size_t)(b*NSP + sp)*RRR)*DD + tid;
    #pragma unroll
    for (int s = 0; s < RRR; s++) {
        float v = part[0][s][tid] + part[1][s][tid] +
                  part[2][s][tid] + part[3][s][tid];
        pp[s*DD] = v;
    }
}

// ---------------------------------------------------------------------------
// K_predred: fullrep reduce + norm + nested prefix + cosine; last block
// also computes recon_avg and per-rho means. grid 32, 256 threads.
// ---------------------------------------------------------------------------
__global__ void k_predred(const float* __restrict__ attn, float* __restrict__ out) {
    __shared__ float red[32];
    __shared__ int last_s;
    int b = blockIdx.x, d = threadIdx.x;

    float a = 0.f;
    #pragma unroll
    for (int i = 0; i < 4; i++) a += attn[b*TT + d + 256*i];
    float den = blockReduce256(a, red);
    float fr = 0.f;
    #pragma unroll
    for (int q = 0; q < NFQ; q++) fr += g_frp[(b*NFQ + q)*DD + d];
    fr /= fmaxf(den, 1e-8f);
    float sq0 = blockReduce256(fr*fr, red);
    float nf = fmaxf(sqrtf(sq0), 1e-8f);

    float s0=0.f, s1=0.f, s2=0.f, s3=0.f;
    #pragma unroll
    for (int sp = 0; sp < NSP; sp++) {
        const float* pp = g_pp + ((size_t)(b*NSP + sp)*RRR)*DD + d;
        s0 += pp[0*DD]; s1 += pp[1*DD]; s2 += pp[2*DD]; s3 += pp[3*DD];
    }
    s1 += s0; s2 += s1; s3 += s2;
    float ss[4] = {s0, s1, s2, s3};
    #pragma unroll
    for (int r = 0; r < RRR; r++) {
        float pred = ss[r] / fmaxf(g_den[r*BB + b], 1e-8f);
        float dot = blockReduce256(pred*fr, red);
        float sq  = blockReduce256(pred*pred, red);
        if (d == 0)
            g_ps[r*BB + b] = 1.f - dot/(fmaxf(sqrtf(sq), 1e-8f)*nf);
    }

    if (d == 0) {
        __threadfence();
        int v = atomicAdd(&g_ctr, 1);
        last_s = (v == BB - 1);
    }
    __syncthreads();
    if (last_s) {
        __threadfence();
        if (d == 0) {
            float s = 0.f;
            for (int i = 0; i < RRR*BB; i++) s += g_ps[i];
            out[SCAL_OFF] = s * (1.f/(RRR*BB));
            g_ctr = 0;   // reset for next graph replay
        }
        if (d >= 1 && d <= RRR) {
            int r = d - 1;
            float s = 0.f;
            for (int bb = 0; bb < BB; bb++) s += g_ps[r*BB + bb];
            out[PSM_OFF + r] = s * (1.f/BB);
        }
    }
}

// ---------------------------------------------------------------------------
extern "C" void kernel_launch(void* const* d_in, const int* in_sizes, int n_in,
                              void* d_out, int out_size) {
    const int*   ids  = (const int*)  d_in[0];
    const float* emb  = (const float*)d_in[1];
    const float* attn = (const float*)d_in[2];
    const float* lnw  = (const float*)d_in[3];
    const float* lnb  = (const float*)d_in[4];
    const float* w1   = (const float*)d_in[5];
    const float* b1   = (const float*)d_in[6];
    const float* w2   = (const float*)d_in[7];
    const float* b2   = (const float*)d_in[8];
    const float* tbl  = (const float*)d_in[9];
    float* out = (float*)d_out;

    cudaFuncSetAttribute(k_mma, cudaFuncAttributeMaxDynamicSharedMemorySize,
                         MMA_SMEM);

    k_split<<<512 + NPAD, 256>>>(emb, attn, lnw, lnb, w1, b1, w2);
    k_mma<<<NROWS/128, 512, MMA_SMEM>>>(b2);
    k_rank1<<<dim3(BB, 8), TT>>>(attn);
    k_rank2<<<BB, TT>>>(attn, out);
    k_predpart<<<dim3(BB, NSP), 256>>>(attn, ids, tbl);
    k_predred<<<BB, 256>>>(attn, out);
}

// round 16
// speedup vs baseline: 1.0557x; 1.0011x over previous
#include <cuda_runtime.h>
#include <cuda_fp16.h>
#include <math.h>
#include <stdint.h>

#define BB 32
#define TT 1024
#define DD 256
#define HH 341
#define RRR 4
#define NSP 32
#define NFQ 16
#define NRC 16          // rank chunks
#define NPAD 352        // H padded to 352
#define NROWS (BB*TT)   // 32768

// Output layout
#define HARD_OFF  (BB*TT)
#define SCAL_OFF  (HARD_OFF + RRR*BB*TT)
#define PSM_OFF   (SCAL_OFF + 1)
#define RHOE_OFF  (PSM_OFF + RRR)

// Device scratch
__device__ __half g_x0[NROWS*DD];      // fp16 hi of LN output
__device__ __half g_x1[NROWS*DD];      // fp16 residual
__device__ __half g_w0t[NPAD*DD];      // [n][k] transposed w1 hi
__device__ __half g_w1t[NPAD*DD];      // [n][k] transposed w1 residual
__device__ float g_b1p[NPAD];
__device__ float g_w2p[NPAD];
__device__ float g_scores[BB*TT];
__device__ float g_frp[BB*NFQ*DD];
__device__ int   g_seg[BB*TT];
__device__ float g_den[RRR*BB];
__device__ float g_ps[RRR*BB];
__device__ float g_pp[BB*NSP*RRR*DD];
__device__ unsigned int g_posp[NRC*BB*TT];
__device__ int   g_ctr;                // last-block counter (reset each run)

__constant__ float c_rho[RRR] = {0.1f, 0.25f, 0.5f, 0.75f};

#define SWZ128(x) ((x) ^ (((x) >> 3) & 0x70))

__device__ __forceinline__ uint32_t smem_u32(const void* p) {
    uint32_t a;
    asm("{ .reg .u64 t; cvta.to.shared.u64 t, %1; cvt.u32.u64 %0, t; }"
        : "=r"(a) : "l"(p));
    return a;
}
__device__ __forceinline__ void cp16(uint32_t dst, const void* src) {
    asm volatile("cp.async.cg.shared.global [%0], [%1], 16;"
                 :: "r"(dst), "l"(src));
}
#define CP_COMMIT() asm volatile("cp.async.commit_group;" ::: "memory")
#define CP_WAIT(n)  asm volatile("cp.async.wait_group %0;" :: "n"(n) : "memory")

__device__ __forceinline__ void ldsm_x4(uint32_t& r0, uint32_t& r1,
                                        uint32_t& r2, uint32_t& r3, uint32_t a) {
    asm volatile("ldmatrix.sync.aligned.m8n8.x4.shared.b16 {%0,%1,%2,%3}, [%4];"
                 : "=r"(r0), "=r"(r1), "=r"(r2), "=r"(r3) : "r"(a));
}
__device__ __forceinline__ void ldsm_x2(uint32_t& r0, uint32_t& r1, uint32_t a) {
    asm volatile("ldmatrix.sync.aligned.m8n8.x2.shared.b16 {%0,%1}, [%2];"
                 : "=r"(r0), "=r"(r1) : "r"(a));
}
__device__ __forceinline__ void mma16816(float* c, const uint32_t* a,
                                         const uint32_t* b) {
    asm volatile("mma.sync.aligned.m16n8k16.row.col.f32.f16.f16.f32 "
                 "{%0,%1,%2,%3}, {%4,%5,%6,%7}, {%8,%9}, {%0,%1,%2,%3};"
                 : "+f"(c[0]), "+f"(c[1]), "+f"(c[2]), "+f"(c[3])
                 : "r"(a[0]), "r"(a[1]), "r"(a[2]), "r"(a[3]),
                   "r"(b[0]), "r"(b[1]));
}
__device__ __forceinline__ float gelu_exact(float x) {
    return 0.5f * x * (1.f + erff(x * 0.7071067811865476f));
}

// ---------------------------------------------------------------------------
// Reductions
// ---------------------------------------------------------------------------
__device__ __forceinline__ float blockReduce1024(float v, float* red) {
    int lane = threadIdx.x & 31, w = threadIdx.x >> 5;
    #pragma unroll
    for (int o = 16; o; o >>= 1) v += __shfl_xor_sync(0xffffffffu, v, o);
    __syncthreads();
    if (lane == 0) red[w] = v;
    __syncthreads();
    if (w == 0) {
        float s = red[lane];
        #pragma unroll
        for (int o = 16; o; o >>= 1) s += __shfl_xor_sync(0xffffffffu, s, o);
        if (lane == 0) red[0] = s;
    }
    __syncthreads();
    return red[0];
}
__device__ __forceinline__ float blockReduce256(float v, float* red) {
    int lane = threadIdx.x & 31, w = threadIdx.x >> 5;
    #pragma unroll
    for (int o = 16; o; o >>= 1) v += __shfl_xor_sync(0xffffffffu, v, o);
    __syncthreads();
    if (lane == 0) red[w] = v;
    __syncthreads();
    if (w == 0) {
        float s = (lane < 8) ? red[lane] : 0.f;
        #pragma unroll
        for (int o = 16; o; o >>= 1) s += __shfl_xor_sync(0xffffffffu, s, o);
        if (lane == 0) red[0] = s;
    }
    __syncthreads();
    return red[0];
}

// ---------------------------------------------------------------------------
// K_split (fused with wsplit): blocks [0,512) do LN+fp16x2 split + fullrep
// partials; blocks [512, 512+NPAD) transpose+pad+split w1 and pad b1/w2.
// ---------------------------------------------------------------------------
__global__ __launch_bounds__(256) void k_split(const float* __restrict__ emb,
                                               const float* __restrict__ attn,
                                               const float* __restrict__ lnw,
                                               const float* __restrict__ lnb,
                                               const float* __restrict__ w1,
                                               const float* __restrict__ b1,
                                               const float* __restrict__ w2) {
    __shared__ float wacc[8*DD];
    int tid = threadIdx.x;
    if (blockIdx.x >= 512) {
        int n = blockIdx.x - 512, k = tid;
        float v = (n < HH) ? w1[(size_t)k*HH + n] : 0.f;
        __half h0 = __float2half_rn(v);
        float r = v - __half2float(h0);
        __half h1 = __float2half_rn(r);
        g_w0t[n*DD + k] = h0;
        g_w1t[n*DD + k] = h1;
        if (k == 0) {
            g_b1p[n] = (n < HH) ? b1[n] : 0.f;
            g_w2p[n] = (n < HH) ? w2[n] : 0.f;
        }
        return;
    }
    int lane = tid & 31, w = tid >> 5;
    int row0 = blockIdx.x * 64;
    int c0 = lane * 8;
    float lw[8], lb[8];
    #pragma unroll
    for (int i = 0; i < 8; i++) { lw[i] = lnw[c0+i]; lb[i] = lnb[c0+i]; }

    float acc[8] = {0,0,0,0,0,0,0,0};
    for (int rr = 0; rr < 8; rr++) {
        int gr = row0 + w*8 + rr;
        float sel = attn[gr];
        const float4* ep = (const float4*)(emb + (size_t)gr*DD + c0);
        float4 e0 = ep[0], e1 = ep[1];
        float e[8] = {e0.x,e0.y,e0.z,e0.w,e1.x,e1.y,e1.z,e1.w};
        #pragma unroll
        for (int i = 0; i < 8; i++) acc[i] += sel * e[i];
        float x[8]; float s = 0.f;
        #pragma unroll
        for (int i = 0; i < 8; i++) { x[i] = e[i]*sel; s += x[i]; }
        #pragma unroll
        for (int o = 16; o; o >>= 1) s += __shfl_xor_sync(0xffffffffu, s, o);
        float mean = s * (1.f/256.f);
        float v = 0.f;
        #pragma unroll
        for (int i = 0; i < 8; i++) { float dl = x[i]-mean; v += dl*dl; }
        #pragma unroll
        for (int o = 16; o; o >>= 1) v += __shfl_xor_sync(0xffffffffu, v, o);
        float rstd = rsqrtf(v*(1.f/256.f) + 1e-5f);
        unsigned int p0[4], p1[4];
        #pragma unroll
        for (int i = 0; i < 8; i += 2) {
            float ya = (x[i]-mean)*rstd*lw[i] + lb[i];
            float yb = (x[i+1]-mean)*rstd*lw[i+1] + lb[i+1];
            __half a0 = __float2half_rn(ya), b0 = __float2half_rn(yb);
            float ra = ya - __half2float(a0), rb = yb - __half2float(b0);
            __half a1 = __float2half_rn(ra), b1v = __float2half_rn(rb);
            p0[i>>1] = (unsigned int)__half_as_ushort(a0) |
                       ((unsigned int)__half_as_ushort(b0) << 16);
            p1[i>>1] = (unsigned int)__half_as_ushort(a1) |
                       ((unsigned int)__half_as_ushort(b1v) << 16);
        }
        size_t off = (size_t)gr*DD + c0;
        *(uint4*)(g_x0 + off) = make_uint4(p0[0],p0[1],p0[2],p0[3]);
        *(uint4*)(g_x1 + off) = make_uint4(p1[0],p1[1],p1[2],p1[3]);
    }
    #pragma unroll
    for (int i = 0; i < 8; i++) wacc[w*DD + c0 + i] = acc[i];
    __syncthreads();
    float s = 0.f;
    #pragma unroll
    for (int ww = 0; ww < 8; ww++) s += wacc[ww*DD + tid];
    g_frp[(size_t)blockIdx.x*DD + tid] = s;
}

// ---------------------------------------------------------------------------
// K_mma (R8 known-good, FROZEN): fp16 3-pass split GEMM via mma.sync.
// Block 128M x 352N, 512 threads = 16 warps (4m x 4n), warp tile 32x88.
// 3-buffer cp.async pipeline (2 stages in flight, ONE sync per stage).
// ---------------------------------------------------------------------------
#define ABUF 16384
#define BBUF 45056
#define OFF_B0 (3*ABUF)
#define OFF_SC (OFF_B0 + 3*BBUF)
#define MMA_SMEM (OFF_SC + 2048)

__global__ __launch_bounds__(512, 1) void k_mma(const float* __restrict__ b2) {
    extern __shared__ char smem[];
    uint32_t sb = smem_u32(smem);
    int tid = threadIdx.x, lane = tid & 31, wid = tid >> 5;
    int warp_m = wid & 3, warp_n = wid >> 2;
    int row0 = blockIdx.x * 128;

    int sub = lane >> 3, rr = lane & 7;
    uint32_t a_sw[2];
    #pragma unroll
    for (int mt = 0; mt < 2; mt++) {
        int rowA = warp_m*32 + mt*16 + (sub & 1)*8 + rr;
        a_sw[mt] = (uint32_t)(rowA*128 + (((sub >> 1)*16) ^ ((rowA & 7)*16)));
    }
    uint32_t b_sw[6];
    #pragma unroll
    for (int np = 0; np < 5; np++) {
        int rowB = warp_n*88 + np*16 + ((lane >> 3) & 1)*8 + (lane & 7);
        b_sw[np] = (uint32_t)(rowB*128 + (((lane >> 4)*16) ^ ((rowB & 7)*16)));
    }
    {
        int l = lane & 15;
        int rowB = warp_n*88 + 80 + (l & 7);
        b_sw[5] = (uint32_t)(rowB*128 + (((l >> 3)*16) ^ ((rowB & 7)*16)));
    }

    float acc[2][11][4];
    #pragma unroll
    for (int mt = 0; mt < 2; mt++)
        #pragma unroll
        for (int nt = 0; nt < 11; nt++)
            #pragma unroll
            for (int q = 0; q < 4; q++) acc[mt][nt][q] = 0.f;

    auto issue = [&](int s, uint32_t abase, uint32_t bbase) {
        int p = s >> 2, kc = s & 3;
        const __half* asrc = (p == 2) ? g_x1 : g_x0;
        const __half* bsrc = (p == 1) ? g_w1t : g_w0t;
        #pragma unroll
        for (int it = 0; it < 2; it++) {
            int v = it*512 + tid;
            int r = v >> 3, cv = v & 7;
            cp16(abase + SWZ128((uint32_t)(r*128 + cv*16)),
                 asrc + (size_t)(row0 + r)*DD + kc*64 + cv*8);
        }
        #pragma unroll
        for (int it = 0; it < 6; it++) {
            int v = it*512 + tid;
            if (v < 2816) {
                int r = v >> 3, cv = v & 7;
                cp16(bbase + SWZ128((uint32_t)(r*128 + cv*16)),
                     bsrc + (size_t)r*DD + kc*64 + cv*8);
            }
        }
        CP_COMMIT();
    };

    auto compute = [&](uint32_t ab, uint32_t bb) {
        #pragma unroll
        for (int ks = 0; ks < 4; ks++) {
            const uint32_t kx = (uint32_t)(ks*32);
            uint32_t afr[2][4];
            #pragma unroll
            for (int mt = 0; mt < 2; mt++)
                ldsm_x4(afr[mt][0], afr[mt][1], afr[mt][2], afr[mt][3],
                        ab + (a_sw[mt] ^ kx));
            #pragma unroll
            for (int np = 0; np < 5; np++) {
                uint32_t b0a, b1a, b0b, b1b;
                ldsm_x4(b0a, b1a, b0b, b1b, bb + (b_sw[np] ^ kx));
                uint32_t be[2] = {b0a, b0b};
                uint32_t bo[2] = {b1a, b1b};
                mma16816(acc[0][2*np],   afr[0], be);
                mma16816(acc[1][2*np],   afr[1], be);
                mma16816(acc[0][2*np+1], afr[0], bo);
                mma16816(acc[1][2*np+1], afr[1], bo);
            }
            {
                uint32_t b0, b1;
                ldsm_x2(b0, b1, bb + (b_sw[5] ^ kx));
                uint32_t bfr[2] = {b0, b1};
                mma16816(acc[0][10], afr[0], bfr);
                mma16816(acc[1][10], afr[1], bfr);
            }
        }
    };

    issue(0, sb + 0*ABUF, sb + OFF_B0 + 0*BBUF);
    issue(1, sb + 1*ABUF, sb + OFF_B0 + 1*BBUF);
    for (int u = 0; u < 4; u++) {
        CP_WAIT(1); __syncthreads();
        issue(3*u + 2, sb + 2*ABUF, sb + OFF_B0 + 2*BBUF);
        compute(sb + 0*ABUF, sb + OFF_B0 + 0*BBUF);
        CP_WAIT(1); __syncthreads();
        if (u < 3) issue(3*u + 3, sb + 0*ABUF, sb + OFF_B0 + 0*BBUF);
        compute(sb + 1*ABUF, sb + OFF_B0 + 1*BBUF);
        if (u < 3) { CP_WAIT(1); __syncthreads(); }
        else       { CP_WAIT(0); __syncthreads(); }
        if (u < 3) issue(3*u + 4, sb + 1*ABUF, sb + OFF_B0 + 1*BBUF);
        compute(sb + 2*ABUF, sb + OFF_B0 + 2*BBUF);
    }
    __syncthreads();

    int g = lane >> 2, ti = lane & 3;
    float* scb = (float*)(smem + OFF_SC);
    #pragma unroll
    for (int mt = 0; mt < 2; mt++) {
        float s0 = 0.f, s1 = 0.f;
        #pragma unroll
        for (int nt = 0; nt < 11; nt++) {
            int ng = warp_n*88 + nt*8 + ti*2;
            float w2a = g_w2p[ng],   b1a = g_b1p[ng];
            float w2b = g_w2p[ng+1], b1b = g_b1p[ng+1];
            s0 += w2a*gelu_exact(acc[mt][nt][0] + b1a) +
                  w2b*gelu_exact(acc[mt][nt][1] + b1b);
            s1 += w2a*gelu_exact(acc[mt][nt][2] + b1a) +
                  w2b*gelu_exact(acc[mt][nt][3] + b1b);
        }
        s0 += __shfl_xor_sync(0xffffffffu, s0, 1);
        s0 += __shfl_xor_sync(0xffffffffu, s0, 2);
        s1 += __shfl_xor_sync(0xffffffffu, s1, 1);
        s1 += __shfl_xor_sync(0xffffffffu, s1, 2);
        if (ti == 0) {
            scb[warp_n*128 + warp_m*32 + mt*16 + g]     = s0;
            scb[warp_n*128 + warp_m*32 + mt*16 + g + 8] = s1;
        }
    }
    __syncthreads();
    if (tid < 128)
        g_scores[row0 + tid] = scb[tid] + scb[128 + tid] + scb[256 + tid] +
                               scb[384 + tid] + __ldg(b2);
}

// ---------------------------------------------------------------------------
// K_rank1: partial rank-position counts, u32 keys (no idx tiebreak: ties
// occur only among masked tokens whose hard/seg are order-invariant).
// grid (32, NRC=16), 1024 threads, 64 keys per chunk.
// ---------------------------------------------------------------------------
__device__ __forceinline__ unsigned int rank_key32(float a, float sc) {
    if (a == 0.f) return 0xFFFFFFFFu;
    unsigned int u = __float_as_uint(sc);
    return (u & 0x80000000u) ? ~u : (u | 0x80000000u);
}

__global__ void k_rank1(const float* __restrict__ attn) {
    const int CS = TT/NRC;   // 64
    __shared__ unsigned int ck[CS];
    int b = blockIdx.x, c = blockIdx.y, t = threadIdx.x;
    if (t < CS) {
        int i = c*CS + t;
        ck[t] = rank_key32(attn[b*TT + i], g_scores[b*TT + i]);
    }
    __syncthreads();
    unsigned int kt = rank_key32(attn[b*TT + t], g_scores[b*TT + t]);
    int cnt = 0;
    #pragma unroll 16
    for (int j = 0; j < CS; j++) cnt += (ck[j] < kt) ? 1 : 0;
    g_posp[c*(BB*TT) + b*TT + t] = (unsigned int)cnt;
}

// K_rank2: combine counts, hard/seg/outputs. grid 32, 1024 threads.
__global__ void k_rank2(const float* __restrict__ attn, float* __restrict__ out) {
    __shared__ float red[32];
    __shared__ float red8[32*8];
    __shared__ float teff_s;
    int b = blockIdx.x, t = threadIdx.x;
    int lane = t & 31, w = t >> 5;
    float a = attn[b*TT + t];
    unsigned int pos = 0;
    #pragma unroll
    for (int c = 0; c < NRC; c++) pos += g_posp[c*(BB*TT) + b*TT + t];
    float Teff = blockReduce1024(a, red);
    if (t == 0) teff_s = Teff;
    float posf = (float)pos;

    float hard[RRR];
    int seg = RRR;
    #pragma unroll
    for (int r = RRR-1; r >= 0; r--) {
        float kk = rintf(c_rho[r]*Teff);
        kk = (Teff > 0.f) ? fmaxf(kk, 1.f) : 0.f;
        hard[r] = (posf < kk) ? 1.f : 0.f;
        if (hard[r] > 0.f) seg = r;
    }
    g_seg[b*TT + t] = seg;
    out[b*TT + t] = hard[RRR-1];
    #pragma unroll
    for (int r = 0; r < RRR; r++)
        out[HARD_OFF + (r*BB + b)*TT + t] = hard[r];

    float v[8];
    #pragma unroll
    for (int r = 0; r < RRR; r++) { v[r] = a*hard[r]; v[4+r] = hard[r]; }
    #pragma unroll
    for (int j = 0; j < 8; j++)
        #pragma unroll
        for (int o = 16; o; o >>= 1) v[j] += __shfl_xor_sync(0xffffffffu, v[j], o);
    if (lane == 0)
        #pragma unroll
        for (int j = 0; j < 8; j++) red8[w*8 + j] = v[j];
    __syncthreads();
    if (t < 8) {
        float s = 0.f;
        for (int ww = 0; ww < 32; ww++) s += red8[ww*8 + t];
        if (t < 4) g_den[t*BB + b] = s;
        else out[RHOE_OFF + (t-4)*BB + b] = s / fmaxf(teff_s, 1.f);
    }
}

// ---------------------------------------------------------------------------
// K_predpart (v2): float4 gathers, warp-uniform segment branch, seg-4 skip.
// grid (32, NSP=32), 256 threads = 64 dim-groups x 4 token-subsets.
// ---------------------------------------------------------------------------
__global__ __launch_bounds__(256) void k_predpart(const float* __restrict__ attn,
                                                  const int* __restrict__ ids,
                                                  const float* __restrict__ table) {
    const int TS = TT/NSP;   // 32 tokens per block
    __shared__ float wS[TS];
    __shared__ int   sS[TS];
    __shared__ int   iS[TS];
    __shared__ float part[4][RRR][DD];
    int b = blockIdx.x, sp = blockIdx.y, tid = threadIdx.x;
    if (tid < TS) {
        int t = sp*TS + tid;
        int sg = g_seg[b*TT + t];
        sS[tid] = sg;
        wS[tid] = (sg < 4) ? attn[b*TT + t] : 0.f;
        iS[tid] = ids[b*TT + t];
    }
    __syncthreads();

    int dg = tid & 63, sub = tid >> 6;
    float4 a0 = {0,0,0,0}, a1 = {0,0,0,0}, a2 = {0,0,0,0}, a3 = {0,0,0,0};
    #pragma unroll
    for (int u = 0; u < 8; u++) {
        int t = sub*8 + u;
        int sg = sS[t];
        if (sg < 4) {
            float w = wS[t];
            float4 v = __ldg((const float4*)(table + (size_t)iS[t]*DD) + dg);
            float4 wv = make_float4(w*v.x, w*v.y, w*v.z, w*v.w);
            if (sg == 0)      { a0.x += wv.x; a0.y += wv.y; a0.z += wv.z; a0.w += wv.w; }
            else if (sg == 1) { a1.x += wv.x; a1.y += wv.y; a1.z += wv.z; a1.w += wv.w; }
            else if (sg == 2) { a2.x += wv.x; a2.y += wv.y; a2.z += wv.z; a2.w += wv.w; }
            else              { a3.x += wv.x; a3.y += wv.y; a3.z += wv.z; a3.w += wv.w; }
        }
    }
    *(float4*)&part[sub][0][dg*4] = a0;
    *(float4*)&part[sub][1][dg*4] = a1;
    *(float4*)&part[sub][2][dg*4] = a2;
    *(float4*)&part[sub][3][dg*4] = a3;
    __syncthreads();

    float* pp = g_pp + ((size_t)(b*NSP + sp)*RRR)*DD + tid;
    #pragma unroll
    for (int s = 0; s < RRR; s++) {
        float v = part[0][s][tid] + part[1][s][tid] +
                  part[2][s][tid] + part[3][s][tid];
        pp[s*DD] = v;
    }
}

// ---------------------------------------------------------------------------
// K_predred: fullrep reduce + norm + nested prefix + cosine; last block
// also computes recon_avg and per-rho means. grid 32, 256 threads.
// ---------------------------------------------------------------------------
__global__ void k_predred(const float* __restrict__ attn, float* __restrict__ out) {
    __shared__ float red[32];
    __shared__ int last_s;
    int b = blockIdx.x, d = threadIdx.x;

    float a = 0.f;
    #pragma unroll
    for (int i = 0; i < 4; i++) a += attn[b*TT + d + 256*i];
    float den = blockReduce256(a, red);
    float fr = 0.f;
    #pragma unroll
    for (int q = 0; q < NFQ; q++) fr += g_frp[(b*NFQ + q)*DD + d];
    fr /= fmaxf(den, 1e-8f);
    float sq0 = blockReduce256(fr*fr, red);
    float nf = fmaxf(sqrtf(sq0), 1e-8f);

    float s0=0.f, s1=0.f, s2=0.f, s3=0.f;
    #pragma unroll
    for (int sp = 0; sp < NSP; sp++) {
        const float* pp = g_pp + ((size_t)(b*NSP + sp)*RRR)*DD + d;
        s0 += pp[0*DD]; s1 += pp[1*DD]; s2 += pp[2*DD]; s3 += pp[3*DD];
    }
    s1 += s0; s2 += s1; s3 += s2;
    float ss[4] = {s0, s1, s2, s3};
    #pragma unroll
    for (int r = 0; r < RRR; r++) {
        float pred = ss[r] / fmaxf(g_den[r*BB + b], 1e-8f);
        float dot = blockReduce256(pred*fr, red);
        float sq  = blockReduce256(pred*pred, red);
        if (d == 0)
            g_ps[r*BB + b] = 1.f - dot/(fmaxf(sqrtf(sq), 1e-8f)*nf);
    }

    if (d == 0) {
        __threadfence();
        int v = atomicAdd(&g_ctr, 1);
        last_s = (v == BB - 1);
    }
    __syncthreads();
    if (last_s) {
        __threadfence();
        if (d == 0) {
            float s = 0.f;
            for (int i = 0; i < RRR*BB; i++) s += g_ps[i];
            out[SCAL_OFF] = s * (1.f/(RRR*BB));
            g_ctr = 0;   // reset for next graph replay
        }
        if (d >= 1 && d <= RRR) {
            int r = d - 1;
            float s = 0.f;
            for (int bb = 0; bb < BB; bb++) s += g_ps[r*BB + bb];
            out[PSM_OFF + r] = s * (1.f/BB);
        }
    }
}

// ---------------------------------------------------------------------------
extern "C" void kernel_launch(void* const* d_in, const int* in_sizes, int n_in,
                              void* d_out, int out_size) {
    const int*   ids  = (const int*)  d_in[0];
    const float* emb  = (const float*)d_in[1];
    const float* attn = (const float*)d_in[2];
    const float* lnw  = (const float*)d_in[3];
    const float* lnb  = (const float*)d_in[4];
    const float* w1   = (const float*)d_in[5];
    const float* b1   = (const float*)d_in[6];
    const float* w2   = (const float*)d_in[7];
    const float* b2   = (const float*)d_in[8];
    const float* tbl  = (const float*)d_in[9];
    float* out = (float*)d_out;

    cudaFuncSetAttribute(k_mma, cudaFuncAttributeMaxDynamicSharedMemorySize,
                         MMA_SMEM);

    k_split<<<512 + NPAD, 256>>>(emb, attn, lnw, lnb, w1, b1, w2);
    k_mma<<<NROWS/128, 512, MMA_SMEM>>>(b2);
    k_rank1<<<dim3(BB, NRC), TT>>>(attn);
    k_rank2<<<BB, TT>>>(attn, out);
    k_predpart<<<dim3(BB, NSP), 256>>>(attn, ids, tbl);
    k_predred<<<BB, 256>>>(attn, out);
}